// round 12
// baseline (speedup 1.0000x reference)
#include <cuda_runtime.h>
#include <cstdint>
#include <math.h>

#define Dk 128
#define Bk 1024
#define Rk 131072
#define NN 10
#define BN (Bk * NN)          // 10240
#define RNG 8                 // column ranges (stage-1 grid.x)
#define RSPAN (Rk / RNG)      // 16384 cols per CTA
#define SUB 256               // cols per sub-chunk
#define NSUB (RSPAN / SUB)    // 64
#define JBLK 16               // stage-2 j blocks
#define JW 640                // j per stage-2 block
#define QSCALE 254.0f         // fixed queue quant scale (127 / 0.5)

typedef unsigned long long u64;
typedef unsigned int u32;
typedef unsigned short u16;

// ---------------- device scratch ----------------
__device__ float g_feat[2][Bk * Dk];          // normalized fp32 feats [row][d]
__device__ u32   g_featQ[2][Bk * 32];         // int8 feats packed [row][kc]
__device__ u32   g_qQ[2][32][Rk];             // int8 queue packed [kc][r]
__device__ int   g_candV[2][Bk * RNG * NN];   // s16-domain top-10 values (desc)
__device__ int   g_candI[2][Bk * RNG * NN];   // matching global col ids
__device__ int   g_topk[2][Bk * NN];
__device__ float g_nnT[2][Dk * BN];           // gathered fp32 [d][j]
__device__ float g_pS[2][Bk][JBLK];
__device__ float g_pP[2][Bk][JBLK];

// ---------------- helpers ----------------
__device__ __forceinline__ void ffma2(u64 &d, u64 a, u64 b) {
    asm("fma.rn.f32x2 %0, %1, %2, %0;" : "+l"(d) : "l"(a), "l"(b));
}
__device__ __forceinline__ u64 dupf(float f) {
    u64 r; unsigned u = __float_as_uint(f);
    asm("mov.b64 %0, {%1, %2};" : "=l"(r) : "r"(u), "r"(u));
    return r;
}
__device__ __forceinline__ float2 unpack2(u64 a) {
    float2 o;
    asm("mov.b64 {%0, %1}, %2;" : "=f"(o.x), "=f"(o.y) : "l"(a));
    return o;
}
__device__ __forceinline__ u32 smem_u32(const void* p) {
    u32 a;
    asm("{ .reg .u64 t; cvta.to.shared.u64 t, %1; cvt.u32.u64 %0, t; }"
        : "=r"(a) : "l"(p));
    return a;
}
#define CP_ASYNC16(sdst, gsrc) \
    asm volatile("cp.async.cg.shared.global [%0], [%1], 16;" \
                 :: "r"(sdst), "l"(gsrc) : "memory")
#define CP_COMMIT() asm volatile("cp.async.commit_group;" ::: "memory")
#define CP_WAIT0()  asm volatile("cp.async.wait_group 0;" ::: "memory")

// ---------------- 1. normalize rows + int8 pack ---------------------------------
__global__ void normalize_kernel(const float* __restrict__ fX,
                                 const float* __restrict__ fY) {
    int side = blockIdx.y;
    int row = blockIdx.x;
    int d = threadIdx.x;
    const float* in = side ? fY : fX;
    float v = in[row * Dk + d];
    float sq = v * v;
    #pragma unroll
    for (int o = 16; o; o >>= 1) sq += __shfl_xor_sync(0xFFFFFFFFu, sq, o);
    __shared__ float ws[4], wm[4];
    __shared__ float nrm, smx;
    __shared__ unsigned char sb8[128];
    if ((d & 31) == 0) ws[d >> 5] = sq;
    __syncthreads();
    if (d == 0) nrm = sqrtf(ws[0] + ws[1] + ws[2] + ws[3]);
    __syncthreads();
    float nv = v / nrm;
    g_feat[side][row * Dk + d] = nv;
    float av = fabsf(nv);
    #pragma unroll
    for (int o = 16; o; o >>= 1) av = fmaxf(av, __shfl_xor_sync(0xFFFFFFFFu, av, o));
    if ((d & 31) == 0) wm[d >> 5] = av;
    __syncthreads();
    if (d == 0) smx = fmaxf(fmaxf(wm[0], wm[1]), fmaxf(wm[2], wm[3]));
    __syncthreads();
    int q = __float2int_rn(nv * (127.f / smx));
    sb8[d] = (unsigned char)(signed char)q;
    __syncthreads();
    if (d < 32) {
        u32 p = (u32)sb8[4 * d] | ((u32)sb8[4 * d + 1] << 8) |
                ((u32)sb8[4 * d + 2] << 16) | ((u32)sb8[4 * d + 3] << 24);
        g_featQ[side][row * 32 + d] = p;   // [row][kc]
    }
}

// ---------------- 2. transpose + fixed-scale int8 quantize queue ----------------
__global__ void transposeQ_kernel(const float* __restrict__ qX,
                                  const float* __restrict__ qY) {
    int side = blockIdx.z;
    const float* src = side ? qX : qY;   // side 0 (feat X) uses queue_Y
    __shared__ float tile[32][33];
    int r0 = blockIdx.x * 32, d0 = blockIdx.y * 32;
    int tx = threadIdx.x, ty = threadIdx.y;
    #pragma unroll
    for (int i = 0; i < 4; ++i)
        tile[ty + i * 8][tx] = src[(size_t)(d0 + ty + i * 8) * Rk + r0 + tx];
    __syncthreads();
    u32 p = 0;
    #pragma unroll
    for (int b = 0; b < 4; ++b) {
        float v = fminf(fmaxf(tile[ty * 4 + b][tx] * QSCALE, -127.f), 127.f);
        int q = __float2int_rn(v);
        p |= ((u32)(unsigned char)(signed char)q) << (8 * b);
    }
    g_qQ[side][(d0 >> 2) + ty][r0 + tx] = p;
}

// ---------------- 3. DP4A sim GEMM + s16 Ss + warp-local scan -------------------
// CTA = 64 rows x 16384-col range, 64 sub-chunks of 256 cols (half the barriers
// and half the A-LDS per dp4a of the 128-col version). Qs double-buffered
// cp.async. Ss (128 cols, s16) is filled+scanned twice per subchunk with only
// warp-local syncs (rows are warp-private).
#define S_QS 0                        // Qs u32 [2][32][256]  = 65536 B
#define S_AS 65536                    // As u32 [64][32]      = 8192 B
#define S_SS 73728                    // Ss s16 [64][136]     = 17408 B
#define S_CV 91136                    // Cv s16 [256][10]     = 5120 B
#define S_CI 96256                    // Ci u16 [256][10]     = 5120 B
#define SMEM1 101376
#define SP1 136

__global__ void __launch_bounds__(256, 2) simtopk_i8_kernel() {
    extern __shared__ char sm[];
    u32 sb = smem_u32(sm);
    u32*   Qs  = reinterpret_cast<u32*>(sm + S_QS);
    u32*   As  = reinterpret_cast<u32*>(sm + S_AS);
    short* Ss  = reinterpret_cast<short*>(sm + S_SS);
    short* CvS = reinterpret_cast<short*>(sm + S_CV);
    u16*   Ci  = reinterpret_cast<u16*>(sm + S_CI);
    int t = threadIdx.x, tx = t & 15, ty = t >> 4;
    int range = blockIdx.x, rt = blockIdx.y, side = blockIdx.z;
    int colBase = range * RSPAN;

    // A tile: [64 rows][32 kc] contiguous copy
    {
        const uint4* src = reinterpret_cast<const uint4*>(&g_featQ[side][rt * 64 * 32]);
        reinterpret_cast<uint4*>(As)[t] = src[t];
        reinterpret_cast<uint4*>(As)[t + 256] = src[t + 256];
    }
    // init persistent lists: thread owns (row = t>>2, seg = t&3)
    short* myCv = CvS + t * 10;
    u16*   myCi = Ci + t * 10;
    #pragma unroll
    for (int k = 0; k < NN; ++k) { myCv[k] = (short)-32768; myCi[k] = 0; }
    int tv9 = -32768;

    // cp.async slot mapping: 8 x 16B of Qs per thread (32 kc rows x 1KB)
    int kcA = t >> 3;                 // kc row
    int cA  = (t & 7) * 8;            // first 16B chunk within row (of 64)
    const char* gQbase = reinterpret_cast<const char*>(&g_qQ[side][0][0]);
    size_t qRowStride = (size_t)Rk * 4;
    u32 sQ0 = sb + S_QS + (u32)(kcA * 1024 + cA * 16);

    // prologue: tile 0 -> buf 0
    {
        const char* gsrc = gQbase + (size_t)kcA * qRowStride +
                           (size_t)colBase * 4 + (size_t)cA * 16;
        #pragma unroll
        for (int j = 0; j < 8; ++j) CP_ASYNC16(sQ0 + j * 16, gsrc + j * 16);
        CP_COMMIT();
    }

    int row = t >> 2, seg = t & 3;

    for (int sc = 0; sc < NSUB; ++sc) {
        CP_WAIT0();
        __syncthreads();   // tile sc visible in smem for all warps

        // prefetch tile sc+1 into alternate buffer (overlaps mainloop)
        if (sc + 1 < NSUB) {
            const char* gsrc = gQbase + (size_t)kcA * qRowStride +
                               (size_t)(colBase + (sc + 1) * SUB) * 4 + (size_t)cA * 16;
            u32 sdst = sQ0 + (u32)(((sc + 1) & 1) * 32768);
            #pragma unroll
            for (int j = 0; j < 8; ++j) CP_ASYNC16(sdst + j * 16, gsrc + j * 16);
        }
        CP_COMMIT();

        const u32* Qb = Qs + (sc & 1) * 8192;

        // mainloop: 4 rows x 16 cols, A via LDS.128 broadcast (1 per 4 kc per row)
        int acc[4][16];
        #pragma unroll
        for (int r = 0; r < 4; ++r)
            #pragma unroll
            for (int c = 0; c < 16; ++c) acc[r][c] = 0;

        #pragma unroll 2
        for (int k4 = 0; k4 < 8; ++k4) {
            uint4 a4[4];
            #pragma unroll
            for (int r = 0; r < 4; ++r)
                a4[r] = *reinterpret_cast<const uint4*>(As + (ty * 4 + r) * 32 + k4 * 4);
            #pragma unroll
            for (int kk = 0; kk < 4; ++kk) {
                const u32* qp = Qb + (k4 * 4 + kk) * 256 + tx * 4;
                uint4 q0 = *reinterpret_cast<const uint4*>(qp);
                uint4 q1 = *reinterpret_cast<const uint4*>(qp + 64);
                uint4 q2 = *reinterpret_cast<const uint4*>(qp + 128);
                uint4 q3 = *reinterpret_cast<const uint4*>(qp + 192);
                #pragma unroll
                for (int r = 0; r < 4; ++r) {
                    int f = (int)((kk == 0) ? a4[r].x : (kk == 1) ? a4[r].y
                                 : (kk == 2) ? a4[r].z : a4[r].w);
                    acc[r][0]  = __dp4a((int)q0.x, f, acc[r][0]);
                    acc[r][1]  = __dp4a((int)q0.y, f, acc[r][1]);
                    acc[r][2]  = __dp4a((int)q0.z, f, acc[r][2]);
                    acc[r][3]  = __dp4a((int)q0.w, f, acc[r][3]);
                    acc[r][4]  = __dp4a((int)q1.x, f, acc[r][4]);
                    acc[r][5]  = __dp4a((int)q1.y, f, acc[r][5]);
                    acc[r][6]  = __dp4a((int)q1.z, f, acc[r][6]);
                    acc[r][7]  = __dp4a((int)q1.w, f, acc[r][7]);
                    acc[r][8]  = __dp4a((int)q2.x, f, acc[r][8]);
                    acc[r][9]  = __dp4a((int)q2.y, f, acc[r][9]);
                    acc[r][10] = __dp4a((int)q2.z, f, acc[r][10]);
                    acc[r][11] = __dp4a((int)q2.w, f, acc[r][11]);
                    acc[r][12] = __dp4a((int)q3.x, f, acc[r][12]);
                    acc[r][13] = __dp4a((int)q3.y, f, acc[r][13]);
                    acc[r][14] = __dp4a((int)q3.z, f, acc[r][14]);
                    acc[r][15] = __dp4a((int)q3.w, f, acc[r][15]);
                }
            }
        }

        // two 128-col halves through the warp-private Ss
        #pragma unroll
        for (int h = 0; h < 2; ++h) {
            #pragma unroll
            for (int g = 0; g < 2; ++g)
                #pragma unroll
                for (int r = 0; r < 4; ++r) {
                    int c0 = h * 8 + g * 4;
                    u32 p0 = __byte_perm((u32)(acc[r][c0 + 0] >> 4),
                                         (u32)(acc[r][c0 + 1] >> 4), 0x5410);
                    u32 p1 = __byte_perm((u32)(acc[r][c0 + 2] >> 4),
                                         (u32)(acc[r][c0 + 3] >> 4), 0x5410);
                    *reinterpret_cast<uint2*>(Ss + (ty * 4 + r) * SP1 + g * 64 + tx * 4) =
                        make_uint2(p0, p1);
                }
            __syncwarp();   // warp-private rows visible to this warp's scan lanes

            // scan: 4 quads of 8 cols (qd = seg + 4j), max-of-8 prefilter
            {
                int cb = sc * SUB + h * 128;
                const short* rowp = Ss + row * SP1;
                #pragma unroll
                for (int j = 0; j < 4; ++j) {
                    int qd = seg + 4 * j;
                    uint4 x = *reinterpret_cast<const uint4*>(rowp + qd * 8);
                    int v0 = (int)(short)x.x, v1 = ((int)x.x) >> 16;
                    int v2 = (int)(short)x.y, v3 = ((int)x.y) >> 16;
                    int v4 = (int)(short)x.z, v5 = ((int)x.z) >> 16;
                    int v6 = (int)(short)x.w, v7 = ((int)x.w) >> 16;
                    int m = max(max(max(v0, v1), max(v2, v3)),
                                max(max(v4, v5), max(v6, v7)));
                    if (m > tv9) {
                        int vv[8] = { v0, v1, v2, v3, v4, v5, v6, v7 };
                        #pragma unroll
                        for (int e = 0; e < 8; ++e) {
                            int val = vv[e];
                            if (val > tv9) {
                                u16 col = (u16)(cb + qd * 8 + e);
                                int pp = 9;
                                while (pp > 0 && (int)myCv[pp - 1] < val) {
                                    myCv[pp] = myCv[pp - 1]; myCi[pp] = myCi[pp - 1]; --pp;
                                }
                                myCv[pp] = (short)val; myCi[pp] = col;
                                tv9 = (int)myCv[9];
                            }
                        }
                    }
                }
            }
            __syncwarp();   // scan reads done before next half's STS
        }
    }
    __syncthreads();

    // merge 4 seg-lists per row -> sorted top-10 -> g_cand (scratch in Qs)
    if (t < 64) {
        int* mv = reinterpret_cast<int*>(Qs) + t * 16;
        int* mi = reinterpret_cast<int*>(Qs) + 1024 + t * 16;
        #pragma unroll
        for (int k = 0; k < NN; ++k) { mv[k] = -2147483647; mi[k] = 0x7fffffff; }
        int m9 = -2147483647; int i9 = 0x7fffffff;
        for (int s = 0; s < 4; ++s) {
            const short* l = CvS + (t * 4 + s) * 10;
            const u16*   li = Ci + (t * 4 + s) * 10;
            #pragma unroll
            for (int k = 0; k < NN; ++k) {
                int v = (int)l[k];
                if (v < m9) break;
                int id = (int)li[k];
                if (v == m9 && id >= i9) continue;
                int pp = 9;
                while (pp > 0 && (mv[pp - 1] < v ||
                                  (mv[pp - 1] == v && mi[pp - 1] > id))) {
                    mv[pp] = mv[pp - 1]; mi[pp] = mi[pp - 1]; --pp;
                }
                mv[pp] = v; mi[pp] = id;
                m9 = mv[9]; i9 = mi[9];
            }
        }
        size_t gb = (((size_t)(rt * 64 + t) * RNG) + range) * NN;
        #pragma unroll
        for (int k = 0; k < NN; ++k) {
            g_candV[side][gb + k] = mv[k];
            g_candI[side][gb + k] = colBase + mi[k];
        }
    }
}

// ---------------- 4. per-row 8-way heads merge -> final top-10 ------------------
__global__ void topk_merge_kernel() {
    __shared__ int cv[64 * 80];
    __shared__ int ci[64 * 80];
    int b = blockIdx.x, side = blockIdx.y, t = threadIdx.x;  // 64 threads
    int row0 = b * 64;
    for (int i = t; i < 64 * 80; i += 64) {
        cv[i] = g_candV[side][(size_t)row0 * 80 + i];
        ci[i] = g_candI[side][(size_t)row0 * 80 + i];
    }
    __syncthreads();
    const int* v = cv + t * 80;
    const int* id = ci + t * 80;
    int cur[8];
    #pragma unroll
    for (int h = 0; h < 8; ++h) cur[h] = h * 10;
    for (int k = 0; k < NN; ++k) {
        int best = -2147483647; int bi = 0x7fffffff; int bh = 0;
        #pragma unroll
        for (int h = 0; h < 8; ++h) {
            int c = cur[h];
            if (c < h * 10 + 10) {
                int x = v[c];
                int xi = id[c];
                if (x > best || (x == best && xi < bi)) { best = x; bi = xi; bh = h; }
            }
        }
        g_topk[side][(row0 + t) * NN + k] = bi;
        #pragma unroll
        for (int h = 0; h < 8; ++h) cur[h] += (h == bh);
    }
}

// ---------------- 5. gather neighbor columns (exact fp32) -----------------------
__global__ void gather_kernel(const float* __restrict__ qX,
                              const float* __restrict__ qY) {
    int j = blockIdx.x * 256 + threadIdx.x;
    int d = blockIdx.y;
    int side = blockIdx.z;
    const float* Q = side ? qX : qY;
    int c = g_topk[side][j];
    g_nnT[side][d * BN + j] = Q[(size_t)d * Rk + c];
}

// ---------------- 6. stage-2 logits GEMM + fixed-max partial LSE ----------------
#define FP 132
#define SM2_F 0
#define SM2_J (64 * FP)
#define SM2_S (SM2_J + 128 * 64)
#define SM2_P (SM2_S + 64)
#define SMEM2_BYTES ((SM2_P + 64) * 4)

__global__ void __launch_bounds__(256, 3) lse_gemm_kernel() {
    extern __shared__ float s2[];
    float* F = s2 + SM2_F;
    float* J = s2 + SM2_J;
    float* accS = s2 + SM2_S;
    float* accP = s2 + SM2_P;
    int t = threadIdx.x;
    int tx = t & 15, ty = t >> 4;
    int rg = blockIdx.x, jb = blockIdx.y, side = blockIdx.z;

    {
        const float* feat = g_feat[side] + rg * 64 * Dk;
        for (int i = t; i < 64 * Dk; i += 256) {
            int r = i >> 7, d = i & 127;
            F[r * FP + d] = feat[i];
        }
        if (t < 64) { accS[t] = 0.f; accP[t] = 0.f; }
    }
    __syncthreads();

    const float4* nn4 = reinterpret_cast<const float4*>(g_nnT[side]);
    for (int jt = 0; jt < JW / 64; ++jt) {
        float4* J4 = reinterpret_cast<float4*>(J);
        #pragma unroll
        for (int i = 0; i < 8; ++i) {
            int lin = i * 256 + t;
            int d = lin >> 4, c4 = lin & 15;
            J4[d * 16 + c4] = nn4[(size_t)d * (BN / 4) + jb * (JW / 4) + jt * 16 + c4];
        }
        __syncthreads();

        u64 acc[4][2];
        #pragma unroll
        for (int r = 0; r < 4; ++r) { acc[r][0] = 0ull; acc[r][1] = 0ull; }
        const float* fb = F + (ty * 4) * FP;
        #pragma unroll 8
        for (int d = 0; d < Dk; ++d) {
            ulonglong2 q = *reinterpret_cast<const ulonglong2*>(J + d * 64 + tx * 4);
            #pragma unroll
            for (int r = 0; r < 4; ++r) {
                u64 fd = dupf(fb[r * FP + d]);
                ffma2(acc[r][0], q.x, fd);
                ffma2(acc[r][1], q.y, fd);
            }
        }

        int j0 = jb * JW + jt * 64 + tx * 4;
        #pragma unroll
        for (int r = 0; r < 4; ++r) {
            float2 a = unpack2(acc[r][0]);
            float2 b2 = unpack2(acc[r][1]);
            float vv[4] = { a.x, a.y, b2.x, b2.y };
            int rowg = rg * 64 + ty * 4 + r;
            float sE = 0.f, sP = 0.f;
            #pragma unroll
            for (int i = 0; i < 4; ++i) {
                float lg = vv[i] * 10.f;            // / TEMP
                sE += __expf(lg - 10.f);            // fixed max = 10 (cos<=1)
                unsigned dj = (unsigned)(j0 + i - rowg * NN);
                if (dj < (unsigned)NN) sP += lg;
            }
            #pragma unroll
            for (int o = 8; o; o >>= 1) {
                sE += __shfl_xor_sync(0xFFFFFFFFu, sE, o);
                sP += __shfl_xor_sync(0xFFFFFFFFu, sP, o);
            }
            if (tx == 0) { accS[ty * 4 + r] += sE; accP[ty * 4 + r] += sP; }
        }
        __syncthreads();
    }
    if (t < 64) {
        int rowg = rg * 64 + t;
        g_pS[side][rowg][jb] = accS[t];
        g_pP[side][rowg][jb] = accP[t];
    }
}

// ---------------- 7. combine partials -> loss ------------------------------------
__global__ void combine_kernel(float* __restrict__ out) {
    __shared__ float red[1024];
    int t = threadIdx.x;
    float term = 0.f;
    #pragma unroll
    for (int side = 0; side < 2; ++side) {
        float S = 0.f, P = 0.f;
        #pragma unroll
        for (int jb = 0; jb < JBLK; ++jb) { S += g_pS[side][t][jb]; P += g_pP[side][t][jb]; }
        term += P - (float)NN * (10.f + logf(S));
    }
    red[t] = term;
    __syncthreads();
    for (int s = 512; s; s >>= 1) {
        if (t < s) red[t] += red[t + s];
        __syncthreads();
    }
    if (t == 0) out[0] = -red[0] / (float)Bk;
}

// ---------------- 8. queue head columns ------------------------------------------
__global__ void qhead_kernel(float* __restrict__ out) {
    int c = blockIdx.x * 256 + threadIdx.x;
    int d = blockIdx.y;
    int side = blockIdx.z;
    out[1 + (size_t)side * Dk * Rk + (size_t)d * Rk + c] = g_feat[side][c * Dk + d];
}

// ---------------- launch ----------------------------------------------------------
extern "C" void kernel_launch(void* const* d_in, const int* in_sizes, int n_in,
                              void* d_out, int out_size) {
    const float* fX = (const float*)d_in[0];
    const float* fY = (const float*)d_in[1];
    const float* qX = (const float*)d_in[2];
    const float* qY = (const float*)d_in[3];
    float* out = (float*)d_out;

    cudaFuncSetAttribute(simtopk_i8_kernel,
                         cudaFuncAttributeMaxDynamicSharedMemorySize, SMEM1);
    cudaFuncSetAttribute(lse_gemm_kernel,
                         cudaFuncAttributeMaxDynamicSharedMemorySize, SMEM2_BYTES);

    normalize_kernel<<<dim3(Bk, 2, 1), Dk>>>(fX, fY);
    transposeQ_kernel<<<dim3(Rk / 32, Dk / 32, 2), dim3(32, 8, 1)>>>(qX, qY);

    simtopk_i8_kernel<<<dim3(RNG, Bk / 64, 2), 256, SMEM1>>>();
    topk_merge_kernel<<<dim3(Bk / 64, 2, 1), 64>>>();
    gather_kernel<<<dim3(BN / 256, Dk, 2), 256>>>(qX, qY);
    lse_gemm_kernel<<<dim3(Bk / 64, JBLK, 2), 256, SMEM2_BYTES>>>();
    combine_kernel<<<1, 1024>>>(out);

    cudaMemcpyAsync(out + 1, qX, (size_t)Dk * Rk * sizeof(float),
                    cudaMemcpyDeviceToDevice, 0);
    cudaMemcpyAsync(out + 1 + (size_t)Dk * Rk, qY, (size_t)Dk * Rk * sizeof(float),
                    cudaMemcpyDeviceToDevice, 0);
    qhead_kernel<<<dim3(Bk / 256, Dk, 2), 256>>>(out);
}

// round 13
// speedup vs baseline: 1.2842x; 1.2842x over previous
#include <cuda_runtime.h>
#include <cstdint>
#include <math.h>

#define Dk 128
#define Bk 1024
#define Rk 131072
#define NN 10
#define BN (Bk * NN)          // 10240
#define RNG 8                 // column ranges (stage-1 grid.x)
#define RSPAN (Rk / RNG)      // 16384 cols per CTA
#define SUB 128               // cols per sub-chunk
#define NSUB (RSPAN / SUB)    // 128
#define JBLK 16               // stage-2 j blocks
#define JW 640                // j per stage-2 block
#define QSCALE 254.0f         // fixed queue quant scale (127 / 0.5)

typedef unsigned long long u64;
typedef unsigned int u32;
typedef unsigned short u16;

// ---------------- device scratch ----------------
__device__ float g_feat[2][Bk * Dk];          // normalized fp32 feats [row][d]
__device__ u32   g_featQ[2][Bk * 32];         // int8 feats packed [row][kc]
__device__ u32   g_qQ[2][32][Rk];             // int8 queue packed [kc][r]
__device__ int   g_candV[2][Bk * RNG * NN];   // int top-10 values (sorted desc)
__device__ int   g_candI[2][Bk * RNG * NN];   // matching global col ids
__device__ int   g_topk[2][Bk * NN];
__device__ float g_nnT[2][Dk * BN];           // gathered fp32 [d][j]
__device__ float g_pS[2][Bk][JBLK];
__device__ float g_pP[2][Bk][JBLK];

// ---------------- helpers ----------------
__device__ __forceinline__ void ffma2(u64 &d, u64 a, u64 b) {
    asm("fma.rn.f32x2 %0, %1, %2, %0;" : "+l"(d) : "l"(a), "l"(b));
}
__device__ __forceinline__ u64 dupf(float f) {
    u64 r; unsigned u = __float_as_uint(f);
    asm("mov.b64 %0, {%1, %2};" : "=l"(r) : "r"(u), "r"(u));
    return r;
}
__device__ __forceinline__ float2 unpack2(u64 a) {
    float2 o;
    asm("mov.b64 {%0, %1}, %2;" : "=f"(o.x), "=f"(o.y) : "l"(a));
    return o;
}
__device__ __forceinline__ u32 smem_u32(const void* p) {
    u32 a;
    asm("{ .reg .u64 t; cvta.to.shared.u64 t, %1; cvt.u32.u64 %0, t; }"
        : "=r"(a) : "l"(p));
    return a;
}
#define CP_ASYNC16(sdst, gsrc) \
    asm volatile("cp.async.cg.shared.global [%0], [%1], 16;" \
                 :: "r"(sdst), "l"(gsrc) : "memory")
#define CP_COMMIT() asm volatile("cp.async.commit_group;" ::: "memory")
#define CP_WAIT0()  asm volatile("cp.async.wait_group 0;" ::: "memory")

// ---------------- 1. normalize rows + int8 pack ---------------------------------
__global__ void normalize_kernel(const float* __restrict__ fX,
                                 const float* __restrict__ fY) {
    int side = blockIdx.y;
    int row = blockIdx.x;
    int d = threadIdx.x;
    const float* in = side ? fY : fX;
    float v = in[row * Dk + d];
    float sq = v * v;
    #pragma unroll
    for (int o = 16; o; o >>= 1) sq += __shfl_xor_sync(0xFFFFFFFFu, sq, o);
    __shared__ float ws[4], wm[4];
    __shared__ float nrm, smx;
    __shared__ unsigned char sb8[128];
    if ((d & 31) == 0) ws[d >> 5] = sq;
    __syncthreads();
    if (d == 0) nrm = sqrtf(ws[0] + ws[1] + ws[2] + ws[3]);
    __syncthreads();
    float nv = v / nrm;
    g_feat[side][row * Dk + d] = nv;
    float av = fabsf(nv);
    #pragma unroll
    for (int o = 16; o; o >>= 1) av = fmaxf(av, __shfl_xor_sync(0xFFFFFFFFu, av, o));
    if ((d & 31) == 0) wm[d >> 5] = av;
    __syncthreads();
    if (d == 0) smx = fmaxf(fmaxf(wm[0], wm[1]), fmaxf(wm[2], wm[3]));
    __syncthreads();
    int q = __float2int_rn(nv * (127.f / smx));
    sb8[d] = (unsigned char)(signed char)q;
    __syncthreads();
    if (d < 32) {
        u32 p = (u32)sb8[4 * d] | ((u32)sb8[4 * d + 1] << 8) |
                ((u32)sb8[4 * d + 2] << 16) | ((u32)sb8[4 * d + 3] << 24);
        g_featQ[side][row * 32 + d] = p;   // [row][kc]
    }
}

// ---------------- 2. transpose + fixed-scale int8 quantize queue ----------------
__global__ void transposeQ_kernel(const float* __restrict__ qX,
                                  const float* __restrict__ qY) {
    int side = blockIdx.z;
    const float* src = side ? qX : qY;   // side 0 (feat X) uses queue_Y
    __shared__ float tile[32][33];
    int r0 = blockIdx.x * 32, d0 = blockIdx.y * 32;
    int tx = threadIdx.x, ty = threadIdx.y;
    #pragma unroll
    for (int i = 0; i < 4; ++i)
        tile[ty + i * 8][tx] = src[(size_t)(d0 + ty + i * 8) * Rk + r0 + tx];
    __syncthreads();
    u32 p = 0;
    #pragma unroll
    for (int b = 0; b < 4; ++b) {
        float v = fminf(fmaxf(tile[ty * 4 + b][tx] * QSCALE, -127.f), 127.f);
        int q = __float2int_rn(v);
        p |= ((u32)(unsigned char)(signed char)q) << (8 * b);
    }
    g_qQ[side][(d0 >> 2) + ty][r0 + tx] = p;
}

// ---------------- 3. DP4A sim GEMM + int Ss redistribution top-10 ---------------
// CTA = 64 rows x 16384-col range. 256 threads (16x16), 128 sub-chunks of 128.
// Qs double-buffered cp.async. Ss stores RAW INT accumulators (fixed queue
// scale -> rank-equivalent). Scan: 1 thread per (row, 32-col contiguous seg),
// 8x LDS.128 + quad-max prefilter, persistent per-thread top-10 list.
#define S_QS 0                        // Qs u32 [2][32][128] = 32768 B
#define S_AS 32768                    // As u32 [64][32]     = 8192 B
#define S_SS 40960                    // Ss int [64][132]    = 33792 B
#define S_CV 74752                    // Cv int [256][10]    = 10240 B
#define S_CI 84992                    // Ci u16 [256][10]    = 5120 B
#define SMEM1 90112
#define SP1 132

__global__ void __launch_bounds__(256, 2) simtopk_i8_kernel() {
    extern __shared__ char sm[];
    u32 sb = smem_u32(sm);
    u32* Qs = reinterpret_cast<u32*>(sm + S_QS);
    u32* As = reinterpret_cast<u32*>(sm + S_AS);
    int* Ss = reinterpret_cast<int*>(sm + S_SS);
    int* Cv = reinterpret_cast<int*>(sm + S_CV);
    u16* Ci = reinterpret_cast<u16*>(sm + S_CI);
    int t = threadIdx.x, tx = t & 15, ty = t >> 4;
    int range = blockIdx.x, rt = blockIdx.y, side = blockIdx.z;
    int colBase = range * RSPAN;

    // A tile: [64 rows][32 kc] contiguous copy
    {
        const uint4* src = reinterpret_cast<const uint4*>(&g_featQ[side][rt * 64 * 32]);
        reinterpret_cast<uint4*>(As)[t] = src[t];
        reinterpret_cast<uint4*>(As)[t + 256] = src[t + 256];
    }
    // init persistent lists: thread owns (row = t>>2, seg = t&3)
    int* myCv = Cv + t * 10;
    u16* myCi = Ci + t * 10;
    #pragma unroll
    for (int k = 0; k < NN; ++k) { myCv[k] = (int)0x80000000; myCi[k] = 0; }
    int tv9 = (int)0x80000000;

    // cp.async slot mapping: 4 x 16B of Qs per thread
    int kcA = t >> 3;
    int c4A = (t * 4) & 31;
    const char* gQbase = reinterpret_cast<const char*>(&g_qQ[side][0][0]);
    size_t qRowStride = (size_t)Rk * 4;
    u32 sQ0 = sb + S_QS + (u32)(kcA * 512 + c4A * 16);

    // prologue: tile 0 -> buf 0
    {
        const char* gsrc = gQbase + (size_t)kcA * qRowStride +
                           (size_t)(colBase + c4A * 4) * 4;
        #pragma unroll
        for (int j = 0; j < 4; ++j) CP_ASYNC16(sQ0 + j * 16, gsrc + j * 16);
        CP_COMMIT();
    }

    int row = t >> 2, seg = t & 3;
    const int* scanBase = Ss + row * SP1 + seg * 32;

    for (int sc = 0; sc < NSUB; ++sc) {
        CP_WAIT0();
        __syncthreads();   // tile sc visible; prev scan's Ss reads done

        // prefetch tile sc+1 into alternate buffer (overlaps mainloop)
        if (sc + 1 < NSUB) {
            const char* gsrc = gQbase + (size_t)kcA * qRowStride +
                               (size_t)(colBase + (sc + 1) * SUB + c4A * 4) * 4;
            u32 sdst = sQ0 + (u32)(((sc + 1) & 1) * 16384);
            #pragma unroll
            for (int j = 0; j < 4; ++j) CP_ASYNC16(sdst + j * 16, gsrc + j * 16);
        }
        CP_COMMIT();

        const u32* Qb = Qs + (sc & 1) * 4096;

        // mainloop: 4 rows x 8 cols, A via LDS.128 broadcast
        int acc[4][8];
        #pragma unroll
        for (int r = 0; r < 4; ++r)
            #pragma unroll
            for (int c = 0; c < 8; ++c) acc[r][c] = 0;

        #pragma unroll 4
        for (int k4 = 0; k4 < 8; ++k4) {
            uint4 a4[4];
            #pragma unroll
            for (int r = 0; r < 4; ++r)
                a4[r] = *reinterpret_cast<const uint4*>(As + (ty * 4 + r) * 32 + k4 * 4);
            #pragma unroll
            for (int kk = 0; kk < 4; ++kk) {
                const u32* qp = Qb + (k4 * 4 + kk) * 128 + tx * 4;
                uint4 q0 = *reinterpret_cast<const uint4*>(qp);
                uint4 q1 = *reinterpret_cast<const uint4*>(qp + 64);
                #pragma unroll
                for (int r = 0; r < 4; ++r) {
                    int f = (int)((kk == 0) ? a4[r].x : (kk == 1) ? a4[r].y
                                 : (kk == 2) ? a4[r].z : a4[r].w);
                    acc[r][0] = __dp4a((int)q0.x, f, acc[r][0]);
                    acc[r][1] = __dp4a((int)q0.y, f, acc[r][1]);
                    acc[r][2] = __dp4a((int)q0.z, f, acc[r][2]);
                    acc[r][3] = __dp4a((int)q0.w, f, acc[r][3]);
                    acc[r][4] = __dp4a((int)q1.x, f, acc[r][4]);
                    acc[r][5] = __dp4a((int)q1.y, f, acc[r][5]);
                    acc[r][6] = __dp4a((int)q1.z, f, acc[r][6]);
                    acc[r][7] = __dp4a((int)q1.w, f, acc[r][7]);
                }
            }
        }

        // write raw int accumulators to Ss (8 STS.128)
        #pragma unroll
        for (int g = 0; g < 2; ++g)
            #pragma unroll
            for (int r = 0; r < 4; ++r) {
                int4 w = make_int4(acc[r][g * 4 + 0], acc[r][g * 4 + 1],
                                   acc[r][g * 4 + 2], acc[r][g * 4 + 3]);
                *reinterpret_cast<int4*>(Ss + (ty * 4 + r) * SP1 + g * 64 + tx * 4) = w;
            }
        __syncthreads();   // Ss visible

        // scan: contiguous 32 cols via 8 LDS.128 + quad-max prefilter
        {
            int cb = sc * SUB + seg * 32;
            #pragma unroll
            for (int qd = 0; qd < 8; ++qd) {
                int4 v = *reinterpret_cast<const int4*>(scanBase + qd * 4);
                int m01 = max(v.x, v.y), m23 = max(v.z, v.w);
                if (max(m01, m23) > tv9) {
                    int vv[4] = { v.x, v.y, v.z, v.w };
                    #pragma unroll
                    for (int e = 0; e < 4; ++e) {
                        int val = vv[e];
                        if (val > tv9) {
                            u16 col = (u16)(cb + qd * 4 + e);
                            int pp = 9;
                            while (pp > 0 && myCv[pp - 1] < val) {
                                myCv[pp] = myCv[pp - 1]; myCi[pp] = myCi[pp - 1]; --pp;
                            }
                            myCv[pp] = val; myCi[pp] = col;
                            tv9 = myCv[9];
                        }
                    }
                }
            }
        }
    }
    __syncthreads();

    // merge 4 seg-lists per row -> sorted top-10 -> g_cand (scratch in Qs)
    if (t < 64) {
        int* mv = reinterpret_cast<int*>(Qs) + t * 16;
        int* mi = reinterpret_cast<int*>(Qs) + 1024 + t * 16;
        #pragma unroll
        for (int k = 0; k < NN; ++k) { mv[k] = (int)0x80000000; mi[k] = 0x7fffffff; }
        int m9 = (int)0x80000000; int i9 = 0x7fffffff;
        for (int s = 0; s < 4; ++s) {
            const int* l = Cv + (t * 4 + s) * 10;
            const u16* li = Ci + (t * 4 + s) * 10;
            #pragma unroll
            for (int k = 0; k < NN; ++k) {
                int v = l[k];
                if (v < m9) break;
                int id = (int)li[k];
                if (v == m9 && id >= i9) continue;
                int pp = 9;
                while (pp > 0 && (mv[pp - 1] < v ||
                                  (mv[pp - 1] == v && mi[pp - 1] > id))) {
                    mv[pp] = mv[pp - 1]; mi[pp] = mi[pp - 1]; --pp;
                }
                mv[pp] = v; mi[pp] = id;
                m9 = mv[9]; i9 = mi[9];
            }
        }
        size_t gb = (((size_t)(rt * 64 + t) * RNG) + range) * NN;
        #pragma unroll
        for (int k = 0; k < NN; ++k) {
            g_candV[side][gb + k] = mv[k];
            g_candI[side][gb + k] = colBase + mi[k];
        }
    }
}

// ---------------- 4. per-row 8-way heads merge -> final top-10 ------------------
__global__ void topk_merge_kernel() {
    __shared__ int cv[64 * 80];
    __shared__ int ci[64 * 80];
    int b = blockIdx.x, side = blockIdx.y, t = threadIdx.x;  // 256 threads
    int row0 = b * 64;
    for (int i = t; i < 64 * 80; i += 256) {
        cv[i] = g_candV[side][(size_t)row0 * 80 + i];
        ci[i] = g_candI[side][(size_t)row0 * 80 + i];
    }
    __syncthreads();
    if (t < 64) {
        const int* v = cv + t * 80;
        const int* id = ci + t * 80;
        int cur[8];
        #pragma unroll
        for (int h = 0; h < 8; ++h) cur[h] = h * 10;
        for (int k = 0; k < NN; ++k) {
            int best = (int)0x80000000; int bi = 0x7fffffff; int bh = 0;
            #pragma unroll
            for (int h = 0; h < 8; ++h) {
                int c = cur[h];
                if (c < h * 10 + 10) {
                    int x = v[c];
                    int xi = id[c];
                    if (x > best || (x == best && xi < bi)) { best = x; bi = xi; bh = h; }
                }
            }
            g_topk[side][(row0 + t) * NN + k] = bi;
            #pragma unroll
            for (int h = 0; h < 8; ++h) cur[h] += (h == bh);
        }
    }
}

// ---------------- 5. gather neighbor columns (exact fp32) -----------------------
__global__ void gather_kernel(const float* __restrict__ qX,
                              const float* __restrict__ qY) {
    int j = blockIdx.x * 256 + threadIdx.x;
    int d = blockIdx.y;
    int side = blockIdx.z;
    const float* Q = side ? qX : qY;
    int c = g_topk[side][j];
    g_nnT[side][d * BN + j] = Q[(size_t)d * Rk + c];
}

// ---------------- 6. stage-2 logits GEMM + fixed-max partial LSE ----------------
#define FP 132
#define SM2_F 0
#define SM2_J (64 * FP)
#define SM2_S (SM2_J + 128 * 64)
#define SM2_P (SM2_S + 64)
#define SMEM2_BYTES ((SM2_P + 64) * 4)

__global__ void __launch_bounds__(256, 3) lse_gemm_kernel() {
    extern __shared__ float s2[];
    float* F = s2 + SM2_F;
    float* J = s2 + SM2_J;
    float* accS = s2 + SM2_S;
    float* accP = s2 + SM2_P;
    int t = threadIdx.x;
    int tx = t & 15, ty = t >> 4;
    int rg = blockIdx.x, jb = blockIdx.y, side = blockIdx.z;

    {
        const float* feat = g_feat[side] + rg * 64 * Dk;
        for (int i = t; i < 64 * Dk; i += 256) {
            int r = i >> 7, d = i & 127;
            F[r * FP + d] = feat[i];
        }
        if (t < 64) { accS[t] = 0.f; accP[t] = 0.f; }
    }
    __syncthreads();

    const float4* nn4 = reinterpret_cast<const float4*>(g_nnT[side]);
    for (int jt = 0; jt < JW / 64; ++jt) {
        float4* J4 = reinterpret_cast<float4*>(J);
        #pragma unroll
        for (int i = 0; i < 8; ++i) {
            int lin = i * 256 + t;
            int d = lin >> 4, c4 = lin & 15;
            J4[d * 16 + c4] = nn4[(size_t)d * (BN / 4) + jb * (JW / 4) + jt * 16 + c4];
        }
        __syncthreads();

        u64 acc[4][2];
        #pragma unroll
        for (int r = 0; r < 4; ++r) { acc[r][0] = 0ull; acc[r][1] = 0ull; }
        const float* fb = F + (ty * 4) * FP;
        #pragma unroll 8
        for (int d = 0; d < Dk; ++d) {
            ulonglong2 q = *reinterpret_cast<const ulonglong2*>(J + d * 64 + tx * 4);
            #pragma unroll
            for (int r = 0; r < 4; ++r) {
                u64 fd = dupf(fb[r * FP + d]);
                ffma2(acc[r][0], q.x, fd);
                ffma2(acc[r][1], q.y, fd);
            }
        }

        int j0 = jb * JW + jt * 64 + tx * 4;
        #pragma unroll
        for (int r = 0; r < 4; ++r) {
            float2 a = unpack2(acc[r][0]);
            float2 b2 = unpack2(acc[r][1]);
            float vv[4] = { a.x, a.y, b2.x, b2.y };
            int rowg = rg * 64 + ty * 4 + r;
            float sE = 0.f, sP = 0.f;
            #pragma unroll
            for (int i = 0; i < 4; ++i) {
                float lg = vv[i] * 10.f;            // / TEMP
                sE += __expf(lg - 10.f);            // fixed max = 10 (cos<=1)
                unsigned dj = (unsigned)(j0 + i - rowg * NN);
                if (dj < (unsigned)NN) sP += lg;
            }
            #pragma unroll
            for (int o = 8; o; o >>= 1) {
                sE += __shfl_xor_sync(0xFFFFFFFFu, sE, o);
                sP += __shfl_xor_sync(0xFFFFFFFFu, sP, o);
            }
            if (tx == 0) { accS[ty * 4 + r] += sE; accP[ty * 4 + r] += sP; }
        }
        __syncthreads();
    }
    if (t < 64) {
        int rowg = rg * 64 + t;
        g_pS[side][rowg][jb] = accS[t];
        g_pP[side][rowg][jb] = accP[t];
    }
}

// ---------------- 7. combine partials -> loss ------------------------------------
__global__ void combine_kernel(float* __restrict__ out) {
    __shared__ float red[1024];
    int t = threadIdx.x;
    float term = 0.f;
    #pragma unroll
    for (int side = 0; side < 2; ++side) {
        float S = 0.f, P = 0.f;
        #pragma unroll
        for (int jb = 0; jb < JBLK; ++jb) { S += g_pS[side][t][jb]; P += g_pP[side][t][jb]; }
        term += P - (float)NN * (10.f + logf(S));
    }
    red[t] = term;
    __syncthreads();
    for (int s = 512; s; s >>= 1) {
        if (t < s) red[t] += red[t + s];
        __syncthreads();
    }
    if (t == 0) out[0] = -red[0] / (float)Bk;
}

// ---------------- 8. queue head columns ------------------------------------------
__global__ void qhead_kernel(float* __restrict__ out) {
    int c = blockIdx.x * 256 + threadIdx.x;
    int d = blockIdx.y;
    int side = blockIdx.z;
    out[1 + (size_t)side * Dk * Rk + (size_t)d * Rk + c] = g_feat[side][c * Dk + d];
}

// ---------------- launch ----------------------------------------------------------
extern "C" void kernel_launch(void* const* d_in, const int* in_sizes, int n_in,
                              void* d_out, int out_size) {
    const float* fX = (const float*)d_in[0];
    const float* fY = (const float*)d_in[1];
    const float* qX = (const float*)d_in[2];
    const float* qY = (const float*)d_in[3];
    float* out = (float*)d_out;

    cudaFuncSetAttribute(simtopk_i8_kernel,
                         cudaFuncAttributeMaxDynamicSharedMemorySize, SMEM1);
    cudaFuncSetAttribute(lse_gemm_kernel,
                         cudaFuncAttributeMaxDynamicSharedMemorySize, SMEM2_BYTES);

    normalize_kernel<<<dim3(Bk, 2, 1), Dk>>>(fX, fY);
    transposeQ_kernel<<<dim3(Rk / 32, Dk / 32, 2), dim3(32, 8, 1)>>>(qX, qY);

    simtopk_i8_kernel<<<dim3(RNG, Bk / 64, 2), 256, SMEM1>>>();
    topk_merge_kernel<<<dim3(Bk / 64, 2, 1), 256>>>();
    gather_kernel<<<dim3(BN / 256, Dk, 2), 256>>>(qX, qY);
    lse_gemm_kernel<<<dim3(Bk / 64, JBLK, 2), 256, SMEM2_BYTES>>>();
    combine_kernel<<<1, 1024>>>(out);

    cudaMemcpyAsync(out + 1, qX, (size_t)Dk * Rk * sizeof(float),
                    cudaMemcpyDeviceToDevice, 0);
    cudaMemcpyAsync(out + 1 + (size_t)Dk * Rk, qY, (size_t)Dk * Rk * sizeof(float),
                    cudaMemcpyDeviceToDevice, 0);
    qhead_kernel<<<dim3(Bk / 256, Dk, 2), 256>>>(out);
}

// round 14
// speedup vs baseline: 1.3461x; 1.0482x over previous
#include <cuda_runtime.h>
#include <cstdint>
#include <math.h>

#define Dk 128
#define Bk 1024
#define Rk 131072
#define NN 10
#define BN (Bk * NN)          // 10240
#define RNG 8                 // column ranges (stage-1 grid.x)
#define RSPAN (Rk / RNG)      // 16384 cols per CTA
#define SUB 128               // cols per sub-chunk
#define NSUB (RSPAN / SUB)    // 128
#define JBLK 16               // stage-2 j blocks
#define JW 640                // j per stage-2 block
#define QSCALE 254.0f         // fixed queue quant scale (127 / 0.5)

typedef unsigned long long u64;
typedef unsigned int u32;
typedef unsigned short u16;

// ---------------- device scratch ----------------
__device__ float g_feat[2][Bk * Dk];          // normalized fp32 feats [row][d]
__device__ u32   g_featQ[2][Bk * 32];         // int8 feats packed [row][kc]
__device__ u32   g_qQ[2][32][Rk];             // int8 queue packed [kc][r]
__device__ int   g_candV[2][Bk * RNG * NN];   // int top-10 values (sorted desc)
__device__ int   g_candI[2][Bk * RNG * NN];   // matching global col ids
__device__ int   g_topk[2][Bk * NN];
__device__ float g_nnT[2][Dk * BN];           // gathered fp32 [d][j]
__device__ float g_pS[2][Bk][JBLK];
__device__ float g_pP[2][Bk][JBLK];

// ---------------- helpers ----------------
__device__ __forceinline__ void ffma2(u64 &d, u64 a, u64 b) {
    asm("fma.rn.f32x2 %0, %1, %2, %0;" : "+l"(d) : "l"(a), "l"(b));
}
__device__ __forceinline__ u64 dupf(float f) {
    u64 r; unsigned u = __float_as_uint(f);
    asm("mov.b64 %0, {%1, %2};" : "=l"(r) : "r"(u), "r"(u));
    return r;
}
__device__ __forceinline__ float2 unpack2(u64 a) {
    float2 o;
    asm("mov.b64 {%0, %1}, %2;" : "=f"(o.x), "=f"(o.y) : "l"(a));
    return o;
}
__device__ __forceinline__ u32 smem_u32(const void* p) {
    u32 a;
    asm("{ .reg .u64 t; cvta.to.shared.u64 t, %1; cvt.u32.u64 %0, t; }"
        : "=r"(a) : "l"(p));
    return a;
}
#define CP_ASYNC16(sdst, gsrc) \
    asm volatile("cp.async.cg.shared.global [%0], [%1], 16;" \
                 :: "r"(sdst), "l"(gsrc) : "memory")
#define CP_COMMIT() asm volatile("cp.async.commit_group;" ::: "memory")
#define CP_WAIT0()  asm volatile("cp.async.wait_group 0;" ::: "memory")

// ---------------- 1. normalize rows + int8 pack ---------------------------------
__global__ void normalize_kernel(const float* __restrict__ fX,
                                 const float* __restrict__ fY) {
    int side = blockIdx.y;
    int row = blockIdx.x;
    int d = threadIdx.x;
    const float* in = side ? fY : fX;
    float v = in[row * Dk + d];
    float sq = v * v;
    #pragma unroll
    for (int o = 16; o; o >>= 1) sq += __shfl_xor_sync(0xFFFFFFFFu, sq, o);
    __shared__ float ws[4], wm[4];
    __shared__ float nrm, smx;
    __shared__ unsigned char sb8[128];
    if ((d & 31) == 0) ws[d >> 5] = sq;
    __syncthreads();
    if (d == 0) nrm = sqrtf(ws[0] + ws[1] + ws[2] + ws[3]);
    __syncthreads();
    float nv = v / nrm;
    g_feat[side][row * Dk + d] = nv;
    float av = fabsf(nv);
    #pragma unroll
    for (int o = 16; o; o >>= 1) av = fmaxf(av, __shfl_xor_sync(0xFFFFFFFFu, av, o));
    if ((d & 31) == 0) wm[d >> 5] = av;
    __syncthreads();
    if (d == 0) smx = fmaxf(fmaxf(wm[0], wm[1]), fmaxf(wm[2], wm[3]));
    __syncthreads();
    int q = __float2int_rn(nv * (127.f / smx));
    sb8[d] = (unsigned char)(signed char)q;
    __syncthreads();
    if (d < 32) {
        u32 p = (u32)sb8[4 * d] | ((u32)sb8[4 * d + 1] << 8) |
                ((u32)sb8[4 * d + 2] << 16) | ((u32)sb8[4 * d + 3] << 24);
        g_featQ[side][row * 32 + d] = p;   // [row][kc]
    }
}

// ---------------- 2. transpose + fixed-scale int8 quantize queue ----------------
__global__ void transposeQ_kernel(const float* __restrict__ qX,
                                  const float* __restrict__ qY) {
    int side = blockIdx.z;
    const float* src = side ? qX : qY;   // side 0 (feat X) uses queue_Y
    __shared__ float tile[32][33];
    int r0 = blockIdx.x * 32, d0 = blockIdx.y * 32;
    int tx = threadIdx.x, ty = threadIdx.y;
    #pragma unroll
    for (int i = 0; i < 4; ++i)
        tile[ty + i * 8][tx] = src[(size_t)(d0 + ty + i * 8) * Rk + r0 + tx];
    __syncthreads();
    u32 p = 0;
    #pragma unroll
    for (int b = 0; b < 4; ++b) {
        float v = fminf(fmaxf(tile[ty * 4 + b][tx] * QSCALE, -127.f), 127.f);
        int q = __float2int_rn(v);
        p |= ((u32)(unsigned char)(signed char)q) << (8 * b);
    }
    g_qQ[side][(d0 >> 2) + ty][r0 + tx] = p;
}

// ---------------- 3. DP4A sim GEMM + int Ss redistribution top-10 ---------------
#define S_QS 0                        // Qs u32 [2][32][128] = 32768 B
#define S_AS 32768                    // As u32 [64][32]     = 8192 B
#define S_SS 40960                    // Ss int [64][132]    = 33792 B
#define S_CV 74752                    // Cv int [256][10]    = 10240 B
#define S_CI 84992                    // Ci u16 [256][10]    = 5120 B
#define SMEM1 90112
#define SP1 132

__global__ void __launch_bounds__(256, 2) simtopk_i8_kernel() {
    extern __shared__ char sm[];
    u32 sb = smem_u32(sm);
    u32* Qs = reinterpret_cast<u32*>(sm + S_QS);
    u32* As = reinterpret_cast<u32*>(sm + S_AS);
    int* Ss = reinterpret_cast<int*>(sm + S_SS);
    int* Cv = reinterpret_cast<int*>(sm + S_CV);
    u16* Ci = reinterpret_cast<u16*>(sm + S_CI);
    int t = threadIdx.x, tx = t & 15, ty = t >> 4;
    int range = blockIdx.x, rt = blockIdx.y, side = blockIdx.z;
    int colBase = range * RSPAN;

    // A tile: [64 rows][32 kc] contiguous copy
    {
        const uint4* src = reinterpret_cast<const uint4*>(&g_featQ[side][rt * 64 * 32]);
        reinterpret_cast<uint4*>(As)[t] = src[t];
        reinterpret_cast<uint4*>(As)[t + 256] = src[t + 256];
    }
    // init persistent lists: thread owns (row = t>>2, seg = t&3)
    int* myCv = Cv + t * 10;
    u16* myCi = Ci + t * 10;
    #pragma unroll
    for (int k = 0; k < NN; ++k) { myCv[k] = (int)0x80000000; myCi[k] = 0; }
    int tv9 = (int)0x80000000;

    // cp.async slot mapping: 4 x 16B of Qs per thread
    int kcA = t >> 3;
    int c4A = (t * 4) & 31;
    const char* gQbase = reinterpret_cast<const char*>(&g_qQ[side][0][0]);
    size_t qRowStride = (size_t)Rk * 4;
    u32 sQ0 = sb + S_QS + (u32)(kcA * 512 + c4A * 16);

    // prologue: tile 0 -> buf 0
    {
        const char* gsrc = gQbase + (size_t)kcA * qRowStride +
                           (size_t)(colBase + c4A * 4) * 4;
        #pragma unroll
        for (int j = 0; j < 4; ++j) CP_ASYNC16(sQ0 + j * 16, gsrc + j * 16);
        CP_COMMIT();
    }

    int row = t >> 2, seg = t & 3;
    const int* scanBase = Ss + row * SP1 + seg * 32;

    for (int sc = 0; sc < NSUB; ++sc) {
        CP_WAIT0();
        __syncthreads();   // tile sc visible; prev scan's Ss reads done

        // prefetch tile sc+1 into alternate buffer (overlaps mainloop)
        if (sc + 1 < NSUB) {
            const char* gsrc = gQbase + (size_t)kcA * qRowStride +
                               (size_t)(colBase + (sc + 1) * SUB + c4A * 4) * 4;
            u32 sdst = sQ0 + (u32)(((sc + 1) & 1) * 16384);
            #pragma unroll
            for (int j = 0; j < 4; ++j) CP_ASYNC16(sdst + j * 16, gsrc + j * 16);
        }
        CP_COMMIT();

        const u32* Qb = Qs + (sc & 1) * 4096;

        // mainloop: 4 rows x 8 cols, A via LDS.128 broadcast
        int acc[4][8];
        #pragma unroll
        for (int r = 0; r < 4; ++r)
            #pragma unroll
            for (int c = 0; c < 8; ++c) acc[r][c] = 0;

        #pragma unroll 2
        for (int k4 = 0; k4 < 8; ++k4) {
            uint4 a4[4];
            #pragma unroll
            for (int r = 0; r < 4; ++r)
                a4[r] = *reinterpret_cast<const uint4*>(As + (ty * 4 + r) * 32 + k4 * 4);
            #pragma unroll
            for (int kk = 0; kk < 4; ++kk) {
                const u32* qp = Qb + (k4 * 4 + kk) * 128 + tx * 4;
                uint4 q0 = *reinterpret_cast<const uint4*>(qp);
                uint4 q1 = *reinterpret_cast<const uint4*>(qp + 64);
                #pragma unroll
                for (int r = 0; r < 4; ++r) {
                    int f = (int)((kk == 0) ? a4[r].x : (kk == 1) ? a4[r].y
                                 : (kk == 2) ? a4[r].z : a4[r].w);
                    acc[r][0] = __dp4a((int)q0.x, f, acc[r][0]);
                    acc[r][1] = __dp4a((int)q0.y, f, acc[r][1]);
                    acc[r][2] = __dp4a((int)q0.z, f, acc[r][2]);
                    acc[r][3] = __dp4a((int)q0.w, f, acc[r][3]);
                    acc[r][4] = __dp4a((int)q1.x, f, acc[r][4]);
                    acc[r][5] = __dp4a((int)q1.y, f, acc[r][5]);
                    acc[r][6] = __dp4a((int)q1.z, f, acc[r][6]);
                    acc[r][7] = __dp4a((int)q1.w, f, acc[r][7]);
                }
            }
        }

        // write raw int accumulators to Ss (8 STS.128)
        #pragma unroll
        for (int g = 0; g < 2; ++g)
            #pragma unroll
            for (int r = 0; r < 4; ++r) {
                int4 w = make_int4(acc[r][g * 4 + 0], acc[r][g * 4 + 1],
                                   acc[r][g * 4 + 2], acc[r][g * 4 + 3]);
                *reinterpret_cast<int4*>(Ss + (ty * 4 + r) * SP1 + g * 64 + tx * 4) = w;
            }
        __syncthreads();   // Ss visible

        // scan: contiguous 32 cols via 8 LDS.128 + quad-max prefilter
        {
            int cb = sc * SUB + seg * 32;
            #pragma unroll
            for (int qd = 0; qd < 8; ++qd) {
                int4 v = *reinterpret_cast<const int4*>(scanBase + qd * 4);
                int m01 = max(v.x, v.y), m23 = max(v.z, v.w);
                if (max(m01, m23) > tv9) {
                    int vv[4] = { v.x, v.y, v.z, v.w };
                    #pragma unroll
                    for (int e = 0; e < 4; ++e) {
                        int val = vv[e];
                        if (val > tv9) {
                            u16 col = (u16)(cb + qd * 4 + e);
                            int pp = 9;
                            while (pp > 0 && myCv[pp - 1] < val) {
                                myCv[pp] = myCv[pp - 1]; myCi[pp] = myCi[pp - 1]; --pp;
                            }
                            myCv[pp] = val; myCi[pp] = col;
                            tv9 = myCv[9];
                        }
                    }
                }
            }
        }
    }
    __syncthreads();

    // merge 4 seg-lists per row -> sorted top-10 -> g_cand (scratch in Qs)
    if (t < 64) {
        int* mv = reinterpret_cast<int*>(Qs) + t * 16;
        int* mi = reinterpret_cast<int*>(Qs) + 1024 + t * 16;
        #pragma unroll
        for (int k = 0; k < NN; ++k) { mv[k] = (int)0x80000000; mi[k] = 0x7fffffff; }
        int m9 = (int)0x80000000; int i9 = 0x7fffffff;
        for (int s = 0; s < 4; ++s) {
            const int* l = Cv + (t * 4 + s) * 10;
            const u16* li = Ci + (t * 4 + s) * 10;
            #pragma unroll
            for (int k = 0; k < NN; ++k) {
                int v = l[k];
                if (v < m9) break;
                int id = (int)li[k];
                if (v == m9 && id >= i9) continue;
                int pp = 9;
                while (pp > 0 && (mv[pp - 1] < v ||
                                  (mv[pp - 1] == v && mi[pp - 1] > id))) {
                    mv[pp] = mv[pp - 1]; mi[pp] = mi[pp - 1]; --pp;
                }
                mv[pp] = v; mi[pp] = id;
                m9 = mv[9]; i9 = mi[9];
            }
        }
        size_t gb = (((size_t)(rt * 64 + t) * RNG) + range) * NN;
        #pragma unroll
        for (int k = 0; k < NN; ++k) {
            g_candV[side][gb + k] = mv[k];
            g_candI[side][gb + k] = colBase + mi[k];
        }
    }
}

// ---------------- 4. per-row 8-way heads merge -> final top-10 ------------------
__global__ void topk_merge_kernel() {
    __shared__ int cv[64 * 80];
    __shared__ int ci[64 * 80];
    int b = blockIdx.x, side = blockIdx.y, t = threadIdx.x;  // 64 threads
    int row0 = b * 64;
    for (int i = t; i < 64 * 80; i += 64) {
        cv[i] = g_candV[side][(size_t)row0 * 80 + i];
        ci[i] = g_candI[side][(size_t)row0 * 80 + i];
    }
    __syncthreads();
    const int* v = cv + t * 80;
    const int* id = ci + t * 80;
    int cur[8];
    #pragma unroll
    for (int h = 0; h < 8; ++h) cur[h] = h * 10;
    for (int k = 0; k < NN; ++k) {
        int best = (int)0x80000000; int bi = 0x7fffffff; int bh = 0;
        #pragma unroll
        for (int h = 0; h < 8; ++h) {
            int c = cur[h];
            if (c < h * 10 + 10) {
                int x = v[c];
                int xi = id[c];
                if (x > best || (x == best && xi < bi)) { best = x; bi = xi; bh = h; }
            }
        }
        g_topk[side][(row0 + t) * NN + k] = bi;
        #pragma unroll
        for (int h = 0; h < 8; ++h) cur[h] += (h == bh);
    }
}

// ---------------- 5. gather neighbor columns (exact fp32) -----------------------
__global__ void gather_kernel(const float* __restrict__ qX,
                              const float* __restrict__ qY) {
    int j = blockIdx.x * 256 + threadIdx.x;
    int d = blockIdx.y;
    int side = blockIdx.z;
    const float* Q = side ? qX : qY;
    int c = g_topk[side][j];
    g_nnT[side][d * BN + j] = Q[(size_t)d * Rk + c];
}

// ---------------- 6. stage-2 logits GEMM + fixed-max partial LSE ----------------
#define FP 132
#define SM2_F 0
#define SM2_J (64 * FP)
#define SM2_S (SM2_J + 128 * 64)
#define SM2_P (SM2_S + 64)
#define SMEM2_BYTES ((SM2_P + 64) * 4)

__global__ void __launch_bounds__(256, 3) lse_gemm_kernel() {
    extern __shared__ float s2[];
    float* F = s2 + SM2_F;
    float* J = s2 + SM2_J;
    float* accS = s2 + SM2_S;
    float* accP = s2 + SM2_P;
    int t = threadIdx.x;
    int tx = t & 15, ty = t >> 4;
    int rg = blockIdx.x, jb = blockIdx.y, side = blockIdx.z;

    {
        const float* feat = g_feat[side] + rg * 64 * Dk;
        for (int i = t; i < 64 * Dk; i += 256) {
            int r = i >> 7, d = i & 127;
            F[r * FP + d] = feat[i];
        }
        if (t < 64) { accS[t] = 0.f; accP[t] = 0.f; }
    }
    __syncthreads();

    const float4* nn4 = reinterpret_cast<const float4*>(g_nnT[side]);
    for (int jt = 0; jt < JW / 64; ++jt) {
        float4* J4 = reinterpret_cast<float4*>(J);
        #pragma unroll
        for (int i = 0; i < 8; ++i) {
            int lin = i * 256 + t;
            int d = lin >> 4, c4 = lin & 15;
            J4[d * 16 + c4] = nn4[(size_t)d * (BN / 4) + jb * (JW / 4) + jt * 16 + c4];
        }
        __syncthreads();

        u64 acc[4][2];
        #pragma unroll
        for (int r = 0; r < 4; ++r) { acc[r][0] = 0ull; acc[r][1] = 0ull; }
        const float* fb = F + (ty * 4) * FP;
        #pragma unroll 8
        for (int d = 0; d < Dk; ++d) {
            ulonglong2 q = *reinterpret_cast<const ulonglong2*>(J + d * 64 + tx * 4);
            #pragma unroll
            for (int r = 0; r < 4; ++r) {
                u64 fd = dupf(fb[r * FP + d]);
                ffma2(acc[r][0], q.x, fd);
                ffma2(acc[r][1], q.y, fd);
            }
        }

        int j0 = jb * JW + jt * 64 + tx * 4;
        #pragma unroll
        for (int r = 0; r < 4; ++r) {
            float2 a = unpack2(acc[r][0]);
            float2 b2 = unpack2(acc[r][1]);
            float vv[4] = { a.x, a.y, b2.x, b2.y };
            int rowg = rg * 64 + ty * 4 + r;
            float sE = 0.f, sP = 0.f;
            #pragma unroll
            for (int i = 0; i < 4; ++i) {
                float lg = vv[i] * 10.f;            // / TEMP
                sE += __expf(lg - 10.f);            // fixed max = 10 (cos<=1)
                unsigned dj = (unsigned)(j0 + i - rowg * NN);
                if (dj < (unsigned)NN) sP += lg;
            }
            #pragma unroll
            for (int o = 8; o; o >>= 1) {
                sE += __shfl_xor_sync(0xFFFFFFFFu, sE, o);
                sP += __shfl_xor_sync(0xFFFFFFFFu, sP, o);
            }
            if (tx == 0) { accS[ty * 4 + r] += sE; accP[ty * 4 + r] += sP; }
        }
        __syncthreads();
    }
    if (t < 64) {
        int rowg = rg * 64 + t;
        g_pS[side][rowg][jb] = accS[t];
        g_pP[side][rowg][jb] = accP[t];
    }
}

// ---------------- 7. combine partials -> loss ------------------------------------
__global__ void combine_kernel(float* __restrict__ out) {
    __shared__ float red[1024];
    int t = threadIdx.x;
    float term = 0.f;
    #pragma unroll
    for (int side = 0; side < 2; ++side) {
        float S = 0.f, P = 0.f;
        #pragma unroll
        for (int jb = 0; jb < JBLK; ++jb) { S += g_pS[side][t][jb]; P += g_pP[side][t][jb]; }
        term += P - (float)NN * (10.f + logf(S));
    }
    red[t] = term;
    __syncthreads();
    for (int s = 512; s; s >>= 1) {
        if (t < s) red[t] += red[t + s];
        __syncthreads();
    }
    if (t == 0) out[0] = -red[0] / (float)Bk;
}

// ---------------- 8. queue head columns ------------------------------------------
__global__ void qhead_kernel(float* __restrict__ out) {
    int c = blockIdx.x * 256 + threadIdx.x;
    int d = blockIdx.y;
    int side = blockIdx.z;
    out[1 + (size_t)side * Dk * Rk + (size_t)d * Rk + c] = g_feat[side][c * Dk + d];
}

// ---------------- launch: fork copies+qhead onto a side stream -------------------
extern "C" void kernel_launch(void* const* d_in, const int* in_sizes, int n_in,
                              void* d_out, int out_size) {
    const float* fX = (const float*)d_in[0];
    const float* fY = (const float*)d_in[1];
    const float* qX = (const float*)d_in[2];
    const float* qY = (const float*)d_in[3];
    float* out = (float*)d_out;

    static cudaStream_t sCopy = nullptr;
    static cudaEvent_t evFork, evNorm, evJoin;
    if (sCopy == nullptr) {
        cudaStreamCreateWithFlags(&sCopy, cudaStreamNonBlocking);
        cudaEventCreateWithFlags(&evFork, cudaEventDisableTiming);
        cudaEventCreateWithFlags(&evNorm, cudaEventDisableTiming);
        cudaEventCreateWithFlags(&evJoin, cudaEventDisableTiming);
        cudaFuncSetAttribute(simtopk_i8_kernel,
                             cudaFuncAttributeMaxDynamicSharedMemorySize, SMEM1);
        cudaFuncSetAttribute(lse_gemm_kernel,
                             cudaFuncAttributeMaxDynamicSharedMemorySize, SMEM2_BYTES);
    }

    // fork side stream off the capture/legacy stream
    cudaEventRecord(evFork, 0);
    cudaStreamWaitEvent(sCopy, evFork, 0);

    // side stream: normalize -> bulk queue copies -> queue-head overwrite
    normalize_kernel<<<dim3(Bk, 2, 1), Dk, 0, sCopy>>>(fX, fY);
    cudaEventRecord(evNorm, sCopy);
    cudaMemcpyAsync(out + 1, qX, (size_t)Dk * Rk * sizeof(float),
                    cudaMemcpyDeviceToDevice, sCopy);
    cudaMemcpyAsync(out + 1 + (size_t)Dk * Rk, qY, (size_t)Dk * Rk * sizeof(float),
                    cudaMemcpyDeviceToDevice, sCopy);
    qhead_kernel<<<dim3(Bk / 256, Dk, 2), 256, 0, sCopy>>>(out);
    cudaEventRecord(evJoin, sCopy);

    // main stream: quantize queue (independent of normalize)
    transposeQ_kernel<<<dim3(Rk / 32, Dk / 32, 2), dim3(32, 8, 1)>>>(qX, qY);
    // need g_feat/g_featQ before simtopk
    cudaStreamWaitEvent(0, evNorm, 0);

    simtopk_i8_kernel<<<dim3(RNG, Bk / 64, 2), 256, SMEM1>>>();
    topk_merge_kernel<<<dim3(Bk / 64, 2, 1), 64>>>();
    gather_kernel<<<dim3(BN / 256, Dk, 2), 256>>>(qX, qY);
    lse_gemm_kernel<<<dim3(Bk / 64, JBLK, 2), 256, SMEM2_BYTES>>>();
    combine_kernel<<<1, 1024>>>(out);

    // join side stream before returning
    cudaStreamWaitEvent(0, evJoin, 0);
}